// round 16
// baseline (speedup 1.0000x reference)
#include <cuda_runtime.h>
#include <cuda.h>
#include <cuda_fp16.h>
#include <cstdint>

#define NNB 32
#define CI  128
#define CO  256
#define HH  56
#define WW  56

// Padded NHWC x in fp16: [n][59 rows][64 cols][128 ci]; rows 1..56 = h 0..55,
// cols 0..55 = w, all padding zero. 128-half front guard for the (h0=0, col -1) read.
__device__ __align__(256) __half g_xt[128 + (size_t)NNB * 59 * 64 * CI];
__device__ __align__(256) __half g_wt[9 * CO * CI];   // [tap][co][ci]

// ---------------- helpers ----------------
__device__ __forceinline__ void cp_async16(uint32_t dst_smem, const void* src) {
    asm volatile("cp.async.cg.shared.global [%0], [%1], 16;" :: "r"(dst_smem), "l"(src) : "memory");
}
#define CP_COMMIT() asm volatile("cp.async.commit_group;" ::: "memory")
#define CP_WAIT0()  asm volatile("cp.async.wait_group 0;" ::: "memory")

#define LDM_X4(r0, r1, r2, r3, addr) \
    asm volatile("ldmatrix.sync.aligned.m8n8.x4.shared.b16 {%0,%1,%2,%3}, [%4];" \
        : "=r"(r0), "=r"(r1), "=r"(r2), "=r"(r3) : "r"(addr))
#define LDM_X2(r0, r1, addr) \
    asm volatile("ldmatrix.sync.aligned.m8n8.x2.shared.b16 {%0,%1}, [%2];" \
        : "=r"(r0), "=r"(r1) : "r"(addr))

__device__ __forceinline__ void mma_f16(float d[4], const uint32_t a[4], uint32_t b0, uint32_t b1) {
    asm volatile(
        "mma.sync.aligned.m16n8k16.row.col.f32.f16.f16.f32 "
        "{%0,%1,%2,%3}, {%4,%5,%6,%7}, {%8,%9}, {%0,%1,%2,%3};"
        : "+f"(d[0]), "+f"(d[1]), "+f"(d[2]), "+f"(d[3])
        : "r"(a[0]), "r"(a[1]), "r"(a[2]), "r"(a[3]), "r"(b0), "r"(b1));
}

// ---------------- weights kernel ----------------
__global__ __launch_bounds__(256)
void weights_kernel(const float* __restrict__ wgt) {
    int idx = blockIdx.x * 256 + threadIdx.x;
    if (idx >= 9 * CO * CI) return;
    int ci  = idx % CI;
    int t   = idx / CI;
    int co  = t % CO;
    int tap = t / CO;
    g_wt[idx] = __float2half_rn(wgt[((size_t)co * CI + ci) * 9 + tap]);
}

// ---------------- xpose kernel ----------------
constexpr int SPITCH = 87;

__global__ __launch_bounds__(256)
void xpose_kernel(const float* __restrict__ x, int n0) {
    const int tid = threadIdx.x;
    const int n   = blockIdx.y + n0;

    __shared__ float s[CI * SPITCH];   // s[ci][87], col offset 2*(ci>>3)
    const int h_p = blockIdx.x;        // 0..58
    const int h   = h_p - 1;
    const bool valid = (h >= 0) && (h < HH);

    if (h_p == 0 && n == 0 && tid < 16)   // front guard (row "-1" of n=0)
        *(uint4*)(g_xt + tid * 8) = make_uint4(0u, 0u, 0u, 0u);

    if (valid) {
        const float* base = x + ((size_t)n * CI * HH + h) * WW;
        for (int idx = tid; idx < CI * WW; idx += 256) {
            const int ci = idx / WW, w = idx - ci * WW;   // lane -> w fast (coalesced)
            s[ci * SPITCH + w + 2 * (ci >> 3)] = base[(size_t)ci * HH * WW + w];
        }
    }
    __syncthreads();

    __half* dst = g_xt + 128 + (size_t)(n * 59 + h_p) * 64 * CI;
    for (int idx = tid; idx < 64 * 16; idx += 256) {
        const int w = idx >> 4;         // 0..63
        const int g = idx & 15;         // ci group of 8
        uint4 v = make_uint4(0u, 0u, 0u, 0u);
        if (valid && w < WW) {
            const float* sp = s + (g * 8) * SPITCH + w + 2 * g;
            float f0 = sp[0 * SPITCH], f1 = sp[1 * SPITCH];
            float f2 = sp[2 * SPITCH], f3 = sp[3 * SPITCH];
            float f4 = sp[4 * SPITCH], f5 = sp[5 * SPITCH];
            float f6 = sp[6 * SPITCH], f7 = sp[7 * SPITCH];
            __half2 p0 = __floats2half2_rn(f0, f1);
            __half2 p1 = __floats2half2_rn(f2, f3);
            __half2 p2 = __floats2half2_rn(f4, f5);
            __half2 p3 = __floats2half2_rn(f6, f7);
            v.x = *(uint32_t*)&p0; v.y = *(uint32_t*)&p1;
            v.z = *(uint32_t*)&p2; v.w = *(uint32_t*)&p3;
        }
        *(uint4*)(dst + (size_t)w * CI + g * 8) = v;
    }
}

// ---------------- main kernel (FROZEN round-10 loop; n-group offset) ----------------
constexpr int B_HALF_BYTES = 250 * 128;              // 32000
constexpr int B_BYTES      = 2 * B_HALF_BYTES;       // 64000
constexpr int A_TILE       = 128 * 64 * 2;           // 16384
constexpr int SMEM_BYTES   = B_BYTES + 2 * A_TILE;   // 96768

__global__ __launch_bounds__(128, 2)
void conv_mma_kernel(float* __restrict__ out, int n0)
{
    extern __shared__ char smem[];
    const uint32_t sm_u = (uint32_t)__cvta_generic_to_shared(smem);
    const uint32_t B_u  = sm_u;
    const uint32_t A_u  = sm_u + B_BYTES;

    const int tid  = threadIdx.x;
    const int lane = tid & 31;
    const int warp = tid >> 5;
    const int g    = lane >> 2;
    const int t    = lane & 3;
    const int warp_m = (warp >> 1) * 64;
    const int warp_n = (warp & 1) * 56;

    const int co_base = blockIdx.x * 128;
    const int h0      = blockIdx.y * 2;
    const int n       = blockIdx.z + n0;

    const __half* xb = g_xt + 128;

    const int quad  = lane >> 3;
    const int rowin = lane & 7;
    const int qlow  = quad & 1;
    const int qhigh = quad >> 1;

    uint32_t aRowB[4];
    #pragma unroll
    for (int mi = 0; mi < 4; mi++)
        aRowB[mi] = (uint32_t)(warp_m + mi * 16 + qlow * 8 + rowin) * 128u;

    uint32_t bRowB[4];
    #pragma unroll
    for (int p = 0; p < 3; p++) {
        const int px = warp_n + (p * 2 + qhigh) * 8 + rowin;
        bRowB[p] = (uint32_t)(px + 8 * (px / 56)) * 128u;
    }
    {
        const int px7 = warp_n + 48 + rowin;
        bRowB[3] = (uint32_t)(px7 + 8 * (px7 / 56)) * 128u;
    }

    float acc[4][7][4];
    #pragma unroll
    for (int mi = 0; mi < 4; mi++)
        #pragma unroll
        for (int ni = 0; ni < 7; ni++)
            #pragma unroll
            for (int r = 0; r < 4; r++) acc[mi][ni][r] = 0.0f;

    {
        const long long F0 = ((long long)(n * 59 + h0) * 64 - 1) * CI;
        #pragma unroll
        for (int half = 0; half < 2; half++) {
            const __half* src = xb + F0 + half * 64;
            const uint32_t dstb = B_u + half * B_HALF_BYTES;
            for (int idx = tid; idx < 250 * 8; idx += 128) {
                const int i = idx >> 3, c = idx & 7;
                cp_async16(dstb + (uint32_t)i * 128u + (uint32_t)((c ^ (i & 7)) * 16),
                           src + (size_t)i * CI + c * 8);
            }
        }
    }

    auto loadA = [&](int kc) {
        const int tap = kc >> 1, cihalf = kc & 1;
        const __half* src = g_wt + (size_t)(tap * CO + co_base) * CI + cihalf * 64;
        const uint32_t dA = A_u + (kc & 1) * A_TILE;
        #pragma unroll
        for (int i = 0; i < 8; i++) {
            const int q = tid + 128 * i;
            const int row = q >> 3, c = q & 7;
            cp_async16(dA + (uint32_t)row * 128u + (uint32_t)((c ^ (row & 7)) * 16),
                       src + (size_t)row * CI + c * 8);
        }
    };

    loadA(0);
    CP_COMMIT();

    #pragma unroll
    for (int kc = 0; kc < 18; kc++) {
        const int tap = kc >> 1, cihalf = kc & 1;
        const int r = tap / 3, s = tap % 3;
        const int off = r * 64 + s;

        CP_WAIT0();
        __syncthreads();

        const uint32_t A  = A_u + (kc & 1) * A_TILE;
        const uint32_t Bo = B_u + cihalf * B_HALF_BYTES + (uint32_t)off * 128u;
        const int ro = (rowin + off) & 7;

        #pragma unroll
        for (int kk = 0; kk < 4; kk++) {
            uint32_t a[4][4];
            #pragma unroll
            for (int mi = 0; mi < 4; mi++)
                LDM_X4(a[mi][0], a[mi][1], a[mi][2], a[mi][3],
                       A + aRowB[mi] + (uint32_t)(((kk * 2 + qhigh) ^ rowin) * 16));
            #pragma unroll
            for (int p = 0; p < 3; p++) {
                uint32_t b0, b1, b2, b3;
                LDM_X4(b0, b1, b2, b3,
                       Bo + bRowB[p] + (uint32_t)(((kk * 2 + qlow) ^ ro) * 16));
                #pragma unroll
                for (int mi = 0; mi < 4; mi++) {
                    mma_f16(acc[mi][2 * p],     a[mi], b0, b1);
                    mma_f16(acc[mi][2 * p + 1], a[mi], b2, b3);
                }
            }
            {
                uint32_t b0, b1;
                LDM_X2(b0, b1,
                       Bo + bRowB[3] + (uint32_t)(((kk * 2 + qlow) ^ ro) * 16));
                #pragma unroll
                for (int mi = 0; mi < 4; mi++)
                    mma_f16(acc[mi][6], a[mi], b0, b1);
            }
            if (kk == 1) {
                if (kc + 1 < 18) loadA(kc + 1);
                CP_COMMIT();
            }
        }
        __syncthreads();
    }

    #pragma unroll
    for (int mi = 0; mi < 4; mi++)
        #pragma unroll
        for (int ni = 0; ni < 7; ni++)
            #pragma unroll
            for (int half = 0; half < 2; half++) {
                const int co = co_base + warp_m + mi * 16 + g + half * 8;
                const int px = warp_n + ni * 8 + 2 * t;
                const int dh = px / 56, w = px % 56;
                float2 v = make_float2(acc[mi][ni][half * 2], acc[mi][ni][half * 2 + 1]);
                *(float2*)&out[(((size_t)n * CO + co) * HH + (h0 + dh)) * WW + w] = v;
            }
}

// ---------------- host: 2-group fork/join DAG ----------------
namespace {
struct GraphCtx {
    cudaStream_t sx = nullptr, sm[2] = {};
    cudaEvent_t  root = nullptr, ex[2] = {}, em[2] = {};
    bool ok = false;
    GraphCtx() {
        bool good = (cudaStreamCreateWithFlags(&sx, cudaStreamNonBlocking) == cudaSuccess);
        for (int i = 0; i < 2; i++)
            good &= (cudaStreamCreateWithFlags(&sm[i], cudaStreamNonBlocking) == cudaSuccess);
        good &= (cudaEventCreateWithFlags(&root, cudaEventDisableTiming) == cudaSuccess);
        for (int i = 0; i < 2; i++) {
            good &= (cudaEventCreateWithFlags(&ex[i], cudaEventDisableTiming) == cudaSuccess);
            good &= (cudaEventCreateWithFlags(&em[i], cudaEventDisableTiming) == cudaSuccess);
        }
        ok = good;
    }
};
GraphCtx g_ctx;
}

extern "C" void kernel_launch(void* const* d_in, const int* in_sizes, int n_in,
                              void* d_out, int out_size)
{
    const float* x   = (const float*)d_in[0];
    const float* wgt = (const float*)d_in[1];
    float*       out = (float*)d_out;

    cudaFuncSetAttribute(conv_mma_kernel, cudaFuncAttributeMaxDynamicSharedMemorySize, SMEM_BYTES);

    if (!g_ctx.ok) {   // fallback: sequential on the launch stream
        weights_kernel<<<(9 * CO * CI + 255) / 256, 256>>>(wgt);
        for (int g = 0; g < 2; g++) xpose_kernel<<<dim3(59, 16), 256>>>(x, g * 16);
        for (int g = 0; g < 2; g++)
            conv_mma_kernel<<<dim3(2, 28, 16), 128, SMEM_BYTES>>>(out, g * 16);
        return;
    }

    // fork from the capture/launch stream
    cudaEventRecord(g_ctx.root, 0);
    cudaStreamWaitEvent(g_ctx.sx, g_ctx.root, 0);

    // producer chain: weights, then 2 xpose groups (in-stream ordered; ex[1]
    // transitively covers group 0, incl. the guard row main g1 reads)
    weights_kernel<<<(9 * CO * CI + 255) / 256, 256, 0, g_ctx.sx>>>(wgt);
    for (int g = 0; g < 2; g++) {
        xpose_kernel<<<dim3(59, 16), 256, 0, g_ctx.sx>>>(x, g * 16);
        cudaEventRecord(g_ctx.ex[g], g_ctx.sx);
    }

    // consumers: each main group gated only by its xpose event
    for (int g = 0; g < 2; g++) {
        cudaStreamWaitEvent(g_ctx.sm[g], g_ctx.ex[g], 0);
        conv_mma_kernel<<<dim3(2, 28, 16), 128, SMEM_BYTES, g_ctx.sm[g]>>>(out, g * 16);
        cudaEventRecord(g_ctx.em[g], g_ctx.sm[g]);
    }

    // join back to the launch stream
    for (int g = 0; g < 2; g++) cudaStreamWaitEvent(0, g_ctx.em[g], 0);
}

// round 17
// speedup vs baseline: 1.0131x; 1.0131x over previous
#include <cuda_runtime.h>
#include <cuda.h>
#include <cuda_fp16.h>
#include <cstdint>

#define NNB 32
#define CI  128
#define CO  256
#define HH  56
#define WW  56

// Padded NHWC x in fp16: [n][59 rows][64 cols][128 ci]; rows 1..56 = h 0..55,
// cols 0..55 = w, all padding zero. 128-half front guard for the (h0=0, col -1) read.
__device__ __align__(256) __half g_xt[128 + (size_t)NNB * 59 * 64 * CI];
__device__ __align__(256) __half g_wt[9 * CO * CI];   // [tap][co][ci]

// ---------------- helpers ----------------
__device__ __forceinline__ void cp_async16(uint32_t dst_smem, const void* src) {
    asm volatile("cp.async.cg.shared.global [%0], [%1], 16;" :: "r"(dst_smem), "l"(src) : "memory");
}
#define CP_COMMIT() asm volatile("cp.async.commit_group;" ::: "memory")
#define CP_WAIT0()  asm volatile("cp.async.wait_group 0;" ::: "memory")

#define LDM_X4(r0, r1, r2, r3, addr) \
    asm volatile("ldmatrix.sync.aligned.m8n8.x4.shared.b16 {%0,%1,%2,%3}, [%4];" \
        : "=r"(r0), "=r"(r1), "=r"(r2), "=r"(r3) : "r"(addr))
#define LDM_X2(r0, r1, addr) \
    asm volatile("ldmatrix.sync.aligned.m8n8.x2.shared.b16 {%0,%1}, [%2];" \
        : "=r"(r0), "=r"(r1) : "r"(addr))

__device__ __forceinline__ void mma_f16(float d[4], const uint32_t a[4], uint32_t b0, uint32_t b1) {
    asm volatile(
        "mma.sync.aligned.m16n8k16.row.col.f32.f16.f16.f32 "
        "{%0,%1,%2,%3}, {%4,%5,%6,%7}, {%8,%9}, {%0,%1,%2,%3};"
        : "+f"(d[0]), "+f"(d[1]), "+f"(d[2]), "+f"(d[3])
        : "r"(a[0]), "r"(a[1]), "r"(a[2]), "r"(a[3]), "r"(b0), "r"(b1));
}

// ---------------- fused prologue (round-8/10 version, known good) ----------------
__global__ __launch_bounds__(256)
void prologue_kernel(const float* __restrict__ x, const float* __restrict__ wgt) {
    const int tid = threadIdx.x;
    const int n   = blockIdx.y;

    if (blockIdx.x == 59) {   // weights
        const int base = n * (9 * CO * CI / NNB);
        for (int k = 0; k < 9 * CO * CI / NNB; k += 256) {
            int idx = base + k + tid;
            int ci  = idx % CI;
            int t   = idx / CI;
            int co  = t % CO;
            int tap = t / CO;
            g_wt[idx] = __float2half_rn(wgt[((size_t)co * CI + ci) * 9 + tap]);
        }
        return;
    }

    __shared__ float s[128][57];
    const int h_p = blockIdx.x;     // 0..58
    const int h   = h_p - 1;
    const bool valid = (h >= 0) && (h < HH);

    if (h_p == 0 && n == 0 && tid < 16)
        *(uint4*)(g_xt + tid * 8) = make_uint4(0u, 0u, 0u, 0u);

    if (valid) {
        for (int idx = tid; idx < CI * WW; idx += 256) {
            int ci = idx / WW, w = idx % WW;
            s[ci][w] = x[(((size_t)n * CI + ci) * HH + h) * WW + w];
        }
    }
    __syncthreads();

    __half* dst = g_xt + 128 + (size_t)(n * 59 + h_p) * 64 * CI;
    for (int idx = tid; idx < 64 * 16; idx += 256) {
        const int w = idx >> 4;
        const int g = idx & 15;
        uint4 v = make_uint4(0u, 0u, 0u, 0u);
        if (valid && w < WW) {
            __half2 p0 = __floats2half2_rn(s[g * 8 + 0][w], s[g * 8 + 1][w]);
            __half2 p1 = __floats2half2_rn(s[g * 8 + 2][w], s[g * 8 + 3][w]);
            __half2 p2 = __floats2half2_rn(s[g * 8 + 4][w], s[g * 8 + 5][w]);
            __half2 p3 = __floats2half2_rn(s[g * 8 + 6][w], s[g * 8 + 7][w]);
            v.x = *(uint32_t*)&p0; v.y = *(uint32_t*)&p1;
            v.z = *(uint32_t*)&p2; v.w = *(uint32_t*)&p3;
        }
        *(uint4*)(dst + (size_t)w * CI + g * 8) = v;
    }
}

// ---------------- main kernel (round-10 + bottom-sync removal ONLY) ----------------
constexpr int B_HALF_BYTES = 250 * 128;              // 32000
constexpr int B_BYTES      = 2 * B_HALF_BYTES;       // 64000
constexpr int A_TILE       = 128 * 64 * 2;           // 16384
constexpr int SMEM_BYTES   = B_BYTES + 2 * A_TILE;   // 96768

__global__ __launch_bounds__(128, 2)
void conv_mma_kernel(float* __restrict__ out)
{
    extern __shared__ char smem[];
    const uint32_t sm_u = (uint32_t)__cvta_generic_to_shared(smem);
    const uint32_t B_u  = sm_u;
    const uint32_t A_u  = sm_u + B_BYTES;

    const int tid  = threadIdx.x;
    const int lane = tid & 31;
    const int warp = tid >> 5;
    const int g    = lane >> 2;
    const int t    = lane & 3;
    const int warp_m = (warp >> 1) * 64;
    const int warp_n = (warp & 1) * 56;

    const int co_base = blockIdx.x * 128;
    const int h0      = blockIdx.y * 2;
    const int n       = blockIdx.z;

    const __half* xb = g_xt + 128;

    const int quad  = lane >> 3;
    const int rowin = lane & 7;
    const int qlow  = quad & 1;
    const int qhigh = quad >> 1;

    uint32_t aRowB[4];
    #pragma unroll
    for (int mi = 0; mi < 4; mi++)
        aRowB[mi] = (uint32_t)(warp_m + mi * 16 + qlow * 8 + rowin) * 128u;

    uint32_t bRowB[4];
    #pragma unroll
    for (int p = 0; p < 3; p++) {
        const int px = warp_n + (p * 2 + qhigh) * 8 + rowin;
        bRowB[p] = (uint32_t)(px + 8 * (px / 56)) * 128u;
    }
    {
        const int px7 = warp_n + 48 + rowin;
        bRowB[3] = (uint32_t)(px7 + 8 * (px7 / 56)) * 128u;
    }

    float acc[4][7][4];
    #pragma unroll
    for (int mi = 0; mi < 4; mi++)
        #pragma unroll
        for (int ni = 0; ni < 7; ni++)
            #pragma unroll
            for (int r = 0; r < 4; r++) acc[mi][ni][r] = 0.0f;

    {
        const long long F0 = ((long long)(n * 59 + h0) * 64 - 1) * CI;
        #pragma unroll
        for (int half = 0; half < 2; half++) {
            const __half* src = xb + F0 + half * 64;
            const uint32_t dstb = B_u + half * B_HALF_BYTES;
            for (int idx = tid; idx < 250 * 8; idx += 128) {
                const int i = idx >> 3, c = idx & 7;
                cp_async16(dstb + (uint32_t)i * 128u + (uint32_t)((c ^ (i & 7)) * 16),
                           src + (size_t)i * CI + c * 8);
            }
        }
    }

    auto loadA = [&](int kc) {
        const int tap = kc >> 1, cihalf = kc & 1;
        const __half* src = g_wt + (size_t)(tap * CO + co_base) * CI + cihalf * 64;
        const uint32_t dA = A_u + (kc & 1) * A_TILE;
        #pragma unroll
        for (int i = 0; i < 8; i++) {
            const int q = tid + 128 * i;
            const int row = q >> 3, c = q & 7;
            cp_async16(dA + (uint32_t)row * 128u + (uint32_t)((c ^ (row & 7)) * 16),
                       src + (size_t)row * CI + c * 8);
        }
    };

    loadA(0);
    CP_COMMIT();

    #pragma unroll
    for (int kc = 0; kc < 18; kc++) {
        const int tap = kc >> 1, cihalf = kc & 1;
        const int r = tap / 3, s = tap % 3;
        const int off = r * 64 + s;

        CP_WAIT0();
        __syncthreads();   // orders: prev chunk fully read by all warps; this
                           // chunk's A slot complete. (Sole barrier per chunk —
                           // the write into slot (kc+1)&1 at kk==1 below happens
                           // strictly after this sync, i.e., after the last
                           // reader of that slot in chunk kc-1.)

        const uint32_t A  = A_u + (kc & 1) * A_TILE;
        const uint32_t Bo = B_u + cihalf * B_HALF_BYTES + (uint32_t)off * 128u;
        const int ro = (rowin + off) & 7;

        #pragma unroll
        for (int kk = 0; kk < 4; kk++) {
            uint32_t a[4][4];
            #pragma unroll
            for (int mi = 0; mi < 4; mi++)
                LDM_X4(a[mi][0], a[mi][1], a[mi][2], a[mi][3],
                       A + aRowB[mi] + (uint32_t)(((kk * 2 + qhigh) ^ rowin) * 16));
            #pragma unroll
            for (int p = 0; p < 3; p++) {
                uint32_t b0, b1, b2, b3;
                LDM_X4(b0, b1, b2, b3,
                       Bo + bRowB[p] + (uint32_t)(((kk * 2 + qlow) ^ ro) * 16));
                #pragma unroll
                for (int mi = 0; mi < 4; mi++) {
                    mma_f16(acc[mi][2 * p],     a[mi], b0, b1);
                    mma_f16(acc[mi][2 * p + 1], a[mi], b2, b3);
                }
            }
            {
                uint32_t b0, b1;
                LDM_X2(b0, b1,
                       Bo + bRowB[3] + (uint32_t)(((kk * 2 + qlow) ^ ro) * 16));
                #pragma unroll
                for (int mi = 0; mi < 4; mi++)
                    mma_f16(acc[mi][6], a[mi], b0, b1);
            }
            if (kk == 1) {
                if (kc + 1 < 18) loadA(kc + 1);
                CP_COMMIT();
            }
        }
        // bottom __syncthreads removed (redundant; see top-sync comment)
    }

    #pragma unroll
    for (int mi = 0; mi < 4; mi++)
        #pragma unroll
        for (int ni = 0; ni < 7; ni++)
            #pragma unroll
            for (int half = 0; half < 2; half++) {
                const int co = co_base + warp_m + mi * 16 + g + half * 8;
                const int px = warp_n + ni * 8 + 2 * t;
                const int dh = px / 56, w = px % 56;
                float2 v = make_float2(acc[mi][ni][half * 2], acc[mi][ni][half * 2 + 1]);
                *(float2*)&out[(((size_t)n * CO + co) * HH + (h0 + dh)) * WW + w] = v;
            }
}

// ---------------- host ----------------
extern "C" void kernel_launch(void* const* d_in, const int* in_sizes, int n_in,
                              void* d_out, int out_size)
{
    const float* x   = (const float*)d_in[0];
    const float* wgt = (const float*)d_in[1];
    float*       out = (float*)d_out;

    prologue_kernel<<<dim3(60, NNB), 256>>>(x, wgt);

    cudaFuncSetAttribute(conv_mma_kernel, cudaFuncAttributeMaxDynamicSharedMemorySize, SMEM_BYTES);
    conv_mma_kernel<<<dim3(2, 28, NNB), 128, SMEM_BYTES>>>(out);
}